// round 13
// baseline (speedup 1.0000x reference)
#include <cuda_runtime.h>
#include <cstdint>

// ---------------- problem constants ----------------
#define BATCH   64
#define MAXH    64
#define MAXW    32
#define DIM     512
#define SGRID   8
#define HID     64

#define TPB       256
#define GRIDMAIN  444      // 3 CTAs/SM x 148 SMs — ALL resident (global barrier safe)
#define NSLICE    8        // 64-d slices
#define TQUOT     55       // tile stride for workers
#define NWORK     (NSLICE * TQUOT)   // 440 worker CTAs
#define QELEMS    (BATCH * MAXH * MAXW * DIM)
#define NROWS     (BATCH * MAXH)     // 4096 (b,i) row units

// SMEM layout (bytes) — eighth-N, point-packed GEMM, canonical in SMEM
#define HT_STRIDE 68       // padded floats per k-row
#define OFF_W2    0        // w2 slice fp32 [64 k][64 d]       (16384)
#define OFF_CAN   16384    // canonical slice [64 pos][64 d]   (16384)
#define OFF_HA    32768    // h_t buf0 [64 k][68]              (17408)
#define OFF_HB    50176    // h_t buf1                         (17408)
#define OFF_B2    67584    // b2 slice [64]                    (256)
#define OFF_M0    67840    // meta buf0 / phase-A u,v          (1024)
#define OFF_M1    68864    // meta buf1 / barrier scratch      (1024)
#define OFF_BASE  69888    // s_base[65]                       (260)
#define OFF_HW    70148    // s_hw[64]                         (256)
#define OFF_W1U   70404
#define OFF_W1V   70660
#define OFF_B1    70916
#define SMEM_BYTES 71424   // x3 = 214272 <= 227KB

typedef unsigned long long ull;

// transposed compacted h: g_h[tile*4096 + k*64 + p]
__device__ __align__(16) float g_h[BATCH * MAXH * MAXW * HID];
__device__ unsigned g_bar = 0;     // rolling global barrier counter

__device__ __forceinline__ float gelu_exact(float x) {
    return 0.5f * x * (1.0f + erff(x * 0.70710678118654752440f));
}

__device__ __forceinline__ ull dupf(float x) {
    ull r;
    unsigned xb = __float_as_uint(x);
    asm("mov.b64 %0, {%1, %1};" : "=l"(r) : "r"(xb));
    return r;
}

// zero/mask one (b,i) row unit
__device__ __forceinline__ void do_row(
    int r, const int* s_hw, float* __restrict__ out,
    float* __restrict__ mout, int tail, int tid)
{
    const int b = r >> 6, i = r & 63;
    const int hw = s_hw[b];
    const int H = hw >> 16, W = hw & 0xFFFF;
    float4* row = (float4*)(out + ((size_t)r) * (MAXW * DIM));
    const float4 z = make_float4(0.f, 0.f, 0.f, 0.f);
    if (i >= H) {
        #pragma unroll
        for (int e = 0; e < (MAXW * DIM / 4) / TPB; e++)   // 16 iters
            row[tid + TPB * e] = z;
    } else if (W < MAXW) {
        int start4 = W * (DIM / 4);
        int cnt4 = (MAXW - W) * (DIM / 4);
        for (int e = tid; e < cnt4; e += TPB)
            row[start4 + e] = z;
    }
    if (tail > 0 && tid < 32) {
        int idx = r * 32 + tid;
        if (idx < tail)
            mout[idx] = (i < H && tid < W) ? 1.0f : 0.0f;
    }
}

// ---------------- single fused persistent kernel ----------------
__global__ __launch_bounds__(TPB, 3) void hgq_all(
    const float* __restrict__ canonical,   // [8,8,512]
    const float* __restrict__ w1,          // [2,64]
    const float* __restrict__ b1,          // [64]
    const float* __restrict__ w2,          // [64,512]
    const float* __restrict__ b2,          // [512]
    const int*   __restrict__ th,
    const int*   __restrict__ tw,
    float*       __restrict__ out,         // [64,64,32,512] (+ mask tail)
    int          out_size)
{
    extern __shared__ char smem[];
    int*   s_base = (int*)(smem + OFF_BASE);   // [65]
    int*   s_hw   = (int*)(smem + OFF_HW);     // [64]
    float* s_w1u  = (float*)(smem + OFF_W1U);
    float* s_w1v  = (float*)(smem + OFF_W1V);
    float* s_b1   = (float*)(smem + OFF_B1);
    volatile unsigned* s_tgt = (unsigned*)(smem + OFF_M1);

    const int tid   = threadIdx.x;
    const int wid   = tid >> 5;
    const int nx    = tid & 31;
    const int bx    = blockIdx.x;
    const bool work = (bx < NWORK);
    const int slice = bx % NSLICE;          // 0..7
    const int t0    = bx / NSLICE;          // 0..55 (workers: 0..54)
    const int tail  = out_size - QELEMS;
    float* mout = out + QELEMS;

    // ---- one-time staging ----
    {
        // w2 slice: [64 k][64 d]
        float4* ws = (float4*)(smem + OFF_W2);
        #pragma unroll
        for (int e = 0; e < 4; e++) {                  // 1024 float4
            int idx = tid + TPB * e;
            int k = idx >> 4, c4 = idx & 15;
            ws[idx - c4 + c4] = __ldg((const float4*)(w2 + k * DIM + slice * 64) + c4);
        }
        // canonical slice: [64 pos][64 d]
        float4* cs = (float4*)(smem + OFF_CAN);
        #pragma unroll
        for (int e = 0; e < 4; e++) {
            int idx = tid + TPB * e;
            int pos = idx >> 4, c4 = idx & 15;
            cs[idx] = __ldg((const float4*)(canonical + pos * DIM + slice * 64) + c4);
        }
        if (tid < 16)
            ((float4*)(smem + OFF_B2))[tid] = __ldg((const float4*)(b2 + slice * 64) + tid);
        if (tid < 64) {
            s_w1u[tid] = __ldg(w1 + tid);
            s_w1v[tid] = __ldg(w1 + HID + tid);
            s_b1[tid]  = __ldg(b1 + tid);
            int H = min(max(__ldg(th + tid), 1), MAXH);
            int W = min(max(__ldg(tw + tid), 1), MAXW);
            s_hw[tid] = (H << 16) | W;
        }
    }
    __syncthreads();

    if (wid == 0) {
        int hw0 = s_hw[2 * nx], hw1 = s_hw[2 * nx + 1];
        int c0 = (hw0 >> 16) * (hw0 & 0xFFFF);
        int c1 = (hw1 >> 16) * (hw1 & 0xFFFF);
        int pair = c0 + c1, incl = pair;
        #pragma unroll
        for (int d = 1; d < 32; d <<= 1) {
            int n = __shfl_up_sync(0xFFFFFFFF, incl, d);
            if (nx >= d) incl += n;
        }
        s_base[2 * nx] = incl - pair;
        s_base[2 * nx + 1] = incl - c1;
        if (nx == 31) s_base[64] = incl;
    }
    __syncthreads();
    const int total = s_base[BATCH];

    // ============ PHASE A: gelu table, written TRANSPOSED [tile][k][p] ============
    {
        float* s_u = (float*)(smem + OFF_M0);
        float* s_v = (float*)(smem + OFF_M0 + 256);
        for (int tt = bx; tt * 64 < total; tt += GRIDMAIN) {
            if (tid < 64) {
                int q = tt * 64 + tid;
                float u = 0.f, v = 0.f;
                if (q < total) {
                    int lo = 0, hi = BATCH;
                    while (hi - lo > 1) {
                        int mid = (lo + hi) >> 1;
                        if (q >= s_base[mid]) lo = mid; else hi = mid;
                    }
                    int hw = s_hw[lo];
                    int H = hw >> 16, W = hw & 0xFFFF;
                    int r = q - s_base[lo];
                    int i = r / W, j = r - i * W;
                    u = (H > 1) ? (float)i / (float)(H - 1) : 0.0f;
                    v = (W > 1) ? (float)j / (float)(W - 1) : 0.0f;
                }
                s_u[tid] = u; s_v[tid] = v;
            }
            __syncthreads();
            {
                int k = tid >> 2, pg = tid & 3;
                float wu = s_w1u[k], wv = s_w1v[k], bk = s_b1[k];
                float* dst = g_h + (size_t)tt * 4096 + k * 64 + pg * 16;
                #pragma unroll
                for (int e = 0; e < 4; e++) {
                    float4 o;
                    int p = pg * 16 + e * 4;
                    o.x = gelu_exact(s_u[p + 0] * wu + s_v[p + 0] * wv + bk);
                    o.y = gelu_exact(s_u[p + 1] * wu + s_v[p + 1] * wv + bk);
                    o.z = gelu_exact(s_u[p + 2] * wu + s_v[p + 2] * wv + bk);
                    o.w = gelu_exact(s_u[p + 3] * wu + s_v[p + 3] * wv + bk);
                    *(float4*)(dst + e * 4) = o;
                }
            }
            __syncthreads();
        }
    }

    // ---- global barrier ----
    __threadfence();
    __syncthreads();
    if (tid == 0) {
        unsigned old = atomicAdd(&g_bar, 1u);
        s_tgt[0] = (old / GRIDMAIN + 1u) * GRIDMAIN;
    }
    __syncthreads();
    const unsigned bar_target = s_tgt[0];
    if (tid == 0) {
        unsigned v;
        do {
            asm volatile("ld.global.acquire.gpu.u32 %0, [%1];"
                         : "=r"(v) : "l"(&g_bar) : "memory");
            if (v >= bar_target) break;
            __nanosleep(64);
        } while (true);
    }
    __syncthreads();

    // ============ PHASE B ============
    auto build = [&](int t, int sel) {
        float* ht = (float*)(smem + (sel ? OFF_HB : OFF_HA));
        char* mb = smem + (sel ? OFF_M1 : OFF_M0);
        int*   m_geom = (int*)mb;
        int*   m_addr = (int*)(mb + 256);
        float* m_wy   = (float*)(mb + 512);
        float* m_wx   = (float*)(mb + 768);

        const float4* src = (const float4*)(g_h + (size_t)t * 4096);
        #pragma unroll
        for (int e = 0; e < 4; e++) {
            int idx = tid + TPB * e;
            float4 v = src[idx];
            int k = idx >> 4, p4 = idx & 15;
            *(float4*)(ht + k * HT_STRIDE + p4 * 4) = v;
        }

        if (tid < 64) {
            int q = t * 64 + tid;
            if (q < total) {
                int lo = 0, hi = BATCH;
                while (hi - lo > 1) {
                    int mid = (lo + hi) >> 1;
                    if (q >= s_base[mid]) lo = mid; else hi = mid;
                }
                int b = lo;
                int hw = s_hw[b];
                int H = hw >> 16, W = hw & 0xFFFF;
                int r = q - s_base[b];
                int i = r / W, j = r - i * W;
                float u = (H > 1) ? (float)i / (float)(H - 1) : 0.0f;
                float v = (W > 1) ? (float)j / (float)(W - 1) : 0.0f;
                float sy = fminf(u * (float)(SGRID - 1), (float)(SGRID - 1));
                float sx = fminf(v * (float)(SGRID - 1), (float)(SGRID - 1));
                int y0 = (int)sy, x0 = (int)sx;
                int y1 = min(y0 + 1, SGRID - 1);
                int x1 = min(x0 + 1, SGRID - 1);
                m_wy[tid] = sy - (float)y0;
                m_wx[tid] = sx - (float)x0;
                m_geom[tid] = y0 | (y1 << 8) | (x0 << 16) | (x1 << 24);
                m_addr[tid] = (b << 11) | (i << 5) | j;
            } else {
                m_wy[tid] = 0.f; m_wx[tid] = 0.f;
                m_geom[tid] = 0;
                m_addr[tid] = -1;
            }
        }
    };

    int zr = bx;       // zero/mask row cursor

    if (work && t0 * 64 < total) build(t0, 0);
    __syncthreads();

    int sel = 0;
    if (work) {
        for (int t = t0; t * 64 < total; t += TQUOT) {
            const float* ht = (const float*)(smem + (sel ? OFF_HB : OFF_HA));
            const char* mb = smem + (sel ? OFF_M1 : OFF_M0);
            const int*   m_geom = (const int*)mb;
            const int*   m_addr = (const int*)(mb + 256);
            const float* m_wy   = (const float*)(mb + 512);
            const float* m_wx   = (const float*)(mb + 768);

            // ---- GEMM: acc[pi][dd] = {out[p_even][d], out[p_odd][d]} ----
            ull acc[4][2];
            #pragma unroll
            for (int pi = 0; pi < 4; pi++) { acc[pi][0] = 0ull; acc[pi][1] = 0ull; }

            const float* w2s = (const float*)(smem + OFF_W2);
            const int dlane = 2 * nx;             // 2 contiguous d per thread

            #pragma unroll 4
            for (int k = 0; k < HID; k++) {
                float2 wq = *(const float2*)(w2s + k * 64 + dlane);
                ull wd0 = dupf(wq.x), wd1 = dupf(wq.y);
                const ulonglong2* hp = (const ulonglong2*)(ht + k * HT_STRIDE + 8 * wid);
                ulonglong2 hA = hp[0], hB = hp[1];
                ull ph0 = hA.x, ph1 = hA.y, ph2 = hB.x, ph3 = hB.y;
                #define FF(pi, ph) \
                    asm("fma.rn.f32x2 %0, %1, %2, %3;" : "=l"(acc[pi][0]) : "l"(ph), "l"(wd0), "l"(acc[pi][0])); \
                    asm("fma.rn.f32x2 %0, %1, %2, %3;" : "=l"(acc[pi][1]) : "l"(ph), "l"(wd1), "l"(acc[pi][1]));
                FF(0, ph0) FF(1, ph1) FF(2, ph2) FF(3, ph3)
                #undef FF
            }

            // ---- epilogue: bilinear from SMEM canonical + acc + b2, STG.64 ----
            {
                const float* scan = (const float*)(smem + OFF_CAN);
                const float2 b2v = *(const float2*)((const float*)(smem + OFF_B2) + dlane);
                const int pbase = wid * 8;

                #pragma unroll
                for (int pi = 0; pi < 4; pi++) {
                    #pragma unroll
                    for (int hlf = 0; hlf < 2; hlf++) {
                        int p = pbase + 2 * pi + hlf;
                        int ad = m_addr[p];
                        if (ad < 0) continue;
                        int geom = m_geom[p];
                        int y0 = geom & 0xFF, y1 = (geom >> 8) & 0xFF;
                        int x0 = (geom >> 16) & 0xFF, x1 = (geom >> 24) & 0xFF;
                        float wy = m_wy[p], wx = m_wx[p];
                        float2 q00 = *(const float2*)(scan + (y0 * SGRID + x0) * 64 + dlane);
                        float2 q01 = *(const float2*)(scan + (y0 * SGRID + x1) * 64 + dlane);
                        float2 q10 = *(const float2*)(scan + (y1 * SGRID + x0) * 64 + dlane);
                        float2 q11 = *(const float2*)(scan + (y1 * SGRID + x1) * 64 + dlane);
                        float w00 = (1.f - wy) * (1.f - wx), w01 = (1.f - wy) * wx;
                        float w10 = wy * (1.f - wx),         w11 = wy * wx;
                        float a0, a1;
                        if (hlf == 0) {
                            a0 = __uint_as_float((unsigned)acc[pi][0]);
                            a1 = __uint_as_float((unsigned)acc[pi][1]);
                        } else {
                            a0 = __uint_as_float((unsigned)(acc[pi][0] >> 32));
                            a1 = __uint_as_float((unsigned)(acc[pi][1] >> 32));
                        }
                        float2 r;
                        r.x = w00 * q00.x + w01 * q01.x + w10 * q10.x + w11 * q11.x + a0 + b2v.x;
                        r.y = w00 * q00.y + w01 * q01.y + w10 * q10.y + w11 * q11.y + a1 + b2v.y;
                        *(float2*)(out + (size_t)ad * DIM + slice * 64 + dlane) = r;
                    }
                }
            }

            // ---- build next tile, interleave one zero/mask row ----
            if ((t + TQUOT) * 64 < total) build(t + TQUOT, sel ^ 1);

            if (zr < NROWS) { do_row(zr, s_hw, out, mout, tail, tid); zr += GRIDMAIN; }

            __syncthreads();
            sel ^= 1;
        }
    }

    // ---- remaining zero/mask rows ----
    #pragma unroll 1
    while (zr < NROWS) { do_row(zr, s_hw, out, mout, tail, tid); zr += GRIDMAIN; }

    // ---- padding past mask region (CTA 0) ----
    if (bx == 0 && tail > NROWS * 32) {
        for (int e = NROWS * 32 + tid; e < tail; e += TPB)
            mout[e] = 0.0f;
    }
}

extern "C" void kernel_launch(void* const* d_in, const int* in_sizes, int n_in,
                              void* d_out, int out_size)
{
    const float* canonical = (const float*)d_in[0];
    const float* w1        = (const float*)d_in[1];
    const float* b1        = (const float*)d_in[2];
    const float* w2        = (const float*)d_in[3];
    const float* b2        = (const float*)d_in[4];
    const int*   th        = (const int*)d_in[6];
    const int*   tw        = (const int*)d_in[7];
    float* out = (float*)d_out;

    cudaFuncSetAttribute(hgq_all, cudaFuncAttributeMaxDynamicSharedMemorySize, SMEM_BYTES);
    hgq_all<<<GRIDMAIN, TPB, SMEM_BYTES>>>(canonical, w1, b1, w2, b2, th, tw,
                                           out, out_size);
}

// round 14
// speedup vs baseline: 1.1987x; 1.1987x over previous
#include <cuda_runtime.h>
#include <cstdint>

// ---------------- problem constants ----------------
#define BATCH   64
#define MAXH    64
#define MAXW    32
#define DIM     512
#define SGRID   8
#define HID     64

#define TPB       256
#define GRIDMAIN  444      // 3 CTAs/SM x 148 SMs — ALL resident (global barrier safe)
#define TSTRIDE   111      // GRIDMAIN / 4 quarters
#define QELEMS    (BATCH * MAXH * MAXW * DIM)
#define NROWS     (BATCH * MAXH)          // 4096 (b,i) row units

// SMEM layout (bytes) — quarter-N, point-packed GEMM
#define HT_STRIDE 68       // padded floats per k-row (16B-aligned, conflict-free)
#define OFF_W2    0        // w2 quarter fp32 [64 k][128 d]          (32768)
#define OFF_HA    32768    // h_t buf0 [64 k][68] fp32               (17408)
#define OFF_HB    50176    // h_t buf1                               (17408)
#define OFF_B2    67584    // b2 quarter [128] fp32                  (512)
#define OFF_M0    68096    // meta buf0 (phase A: s_u/s_v)           (1024)
#define OFF_M1    69120    // meta buf1                              (1024)
#define OFF_BASE  70144    // s_base[65]                             (260)
#define OFF_HW    70404    // s_hw[64]                               (256)
#define OFF_W1U   70660
#define OFF_W1V   70916
#define OFF_B1    71172
#define SMEM_BYTES 71680   // <= ~75.7KB (227KB/3)

typedef unsigned long long ull;

// transposed compacted h: g_h[tile*4096 + k*64 + p]
__device__ __align__(16) float g_h[BATCH * MAXH * MAXW * HID];
__device__ unsigned g_bar = 0;     // rolling global barrier counter

__device__ __forceinline__ float gelu_exact(float x) {
    return 0.5f * x * (1.0f + erff(x * 0.70710678118654752440f));
}

__device__ __forceinline__ ull dupf(float x) {
    ull r;
    unsigned xb = __float_as_uint(x);
    asm("mov.b64 %0, {%1, %1};" : "=l"(r) : "r"(xb));
    return r;
}

// zero/mask one (b,i) row unit
__device__ __forceinline__ void do_row(
    int r, const int* s_hw, float* __restrict__ out,
    float* __restrict__ mout, int tail, int tid)
{
    const int b = r >> 6, i = r & 63;
    const int hw = s_hw[b];
    const int H = hw >> 16, W = hw & 0xFFFF;
    float4* row = (float4*)(out + ((size_t)r) * (MAXW * DIM));
    const float4 z = make_float4(0.f, 0.f, 0.f, 0.f);
    if (i >= H) {
        #pragma unroll
        for (int e = 0; e < (MAXW * DIM / 4) / TPB; e++)   // 16 iters
            row[tid + TPB * e] = z;
    } else if (W < MAXW) {
        int start4 = W * (DIM / 4);
        int cnt4 = (MAXW - W) * (DIM / 4);
        for (int e = tid; e < cnt4; e += TPB)
            row[start4 + e] = z;
    }
    if (tail > 0 && tid < 32) {
        int idx = r * 32 + tid;
        if (idx < tail)
            mout[idx] = (i < H && tid < W) ? 1.0f : 0.0f;
    }
}

// ---------------- single fused persistent kernel ----------------
__global__ __launch_bounds__(TPB, 3) void hgq_all(
    const float* __restrict__ canonical,   // [8,8,512]
    const float* __restrict__ w1,          // [2,64]
    const float* __restrict__ b1,          // [64]
    const float* __restrict__ w2,          // [64,512]
    const float* __restrict__ b2,          // [512]
    const int*   __restrict__ th,
    const int*   __restrict__ tw,
    float*       __restrict__ out,         // [64,64,32,512] (+ mask tail)
    int          out_size)
{
    extern __shared__ char smem[];
    int*   s_base = (int*)(smem + OFF_BASE);   // [65]
    int*   s_hw   = (int*)(smem + OFF_HW);     // [64]
    float* s_w1u  = (float*)(smem + OFF_W1U);
    float* s_w1v  = (float*)(smem + OFF_W1V);
    float* s_b1   = (float*)(smem + OFF_B1);
    volatile unsigned* s_tgt = (unsigned*)(smem + OFF_M1); // scratch for barrier target

    const int tid  = threadIdx.x;
    const int wid  = tid >> 5;
    const int nx   = tid & 31;
    const int qtr  = blockIdx.x & 3;
    const int t0   = blockIdx.x >> 2;
    const int tail = out_size - QELEMS;
    float* mout = out + QELEMS;

    // ---- one-time staging ----
    {
        const float* wsrc = w2 + qtr * 128;
        float4* ws = (float4*)(smem + OFF_W2);
        #pragma unroll
        for (int e = 0; e < 8; e++) {                  // 2048 float4
            int idx = tid + TPB * e;
            int k = idx >> 5, c4 = idx & 31;
            ws[idx] = __ldg((const float4*)(wsrc + k * DIM) + c4);
        }
        if (tid < 32)
            ((float4*)(smem + OFF_B2))[tid] = __ldg((const float4*)(b2 + qtr * 128) + tid);
        if (tid < 64) {
            s_w1u[tid] = __ldg(w1 + tid);
            s_w1v[tid] = __ldg(w1 + HID + tid);
            s_b1[tid]  = __ldg(b1 + tid);
            int H = min(max(__ldg(th + tid), 1), MAXH);
            int W = min(max(__ldg(tw + tid), 1), MAXW);
            s_hw[tid] = (H << 16) | W;
        }
    }
    __syncthreads();

    if (wid == 0) {
        int hw0 = s_hw[2 * nx], hw1 = s_hw[2 * nx + 1];
        int c0 = (hw0 >> 16) * (hw0 & 0xFFFF);
        int c1 = (hw1 >> 16) * (hw1 & 0xFFFF);
        int pair = c0 + c1, incl = pair;
        #pragma unroll
        for (int d = 1; d < 32; d <<= 1) {
            int n = __shfl_up_sync(0xFFFFFFFF, incl, d);
            if (nx >= d) incl += n;
        }
        s_base[2 * nx] = incl - pair;
        s_base[2 * nx + 1] = incl - c1;
        if (nx == 31) s_base[64] = incl;
    }
    __syncthreads();
    const int total = s_base[BATCH];

    // ============ PHASE A: gelu table, written TRANSPOSED [tile][k][p] ============
    {
        float* s_u = (float*)(smem + OFF_M0);
        float* s_v = (float*)(smem + OFF_M0 + 256);
        for (int tt = blockIdx.x; tt * 64 < total; tt += GRIDMAIN) {
            if (tid < 64) {
                int q = tt * 64 + tid;
                float u = 0.f, v = 0.f;
                if (q < total) {
                    int lo = 0, hi = BATCH;
                    while (hi - lo > 1) {
                        int mid = (lo + hi) >> 1;
                        if (q >= s_base[mid]) lo = mid; else hi = mid;
                    }
                    int hw = s_hw[lo];
                    int H = hw >> 16, W = hw & 0xFFFF;
                    int r = q - s_base[lo];
                    int i = r / W, j = r - i * W;
                    u = (H > 1) ? (float)i / (float)(H - 1) : 0.0f;
                    v = (W > 1) ? (float)j / (float)(W - 1) : 0.0f;
                }
                s_u[tid] = u; s_v[tid] = v;
            }
            __syncthreads();
            {
                int k = tid >> 2, pg = tid & 3;
                float wu = s_w1u[k], wv = s_w1v[k], bk = s_b1[k];
                float* dst = g_h + (size_t)tt * 4096 + k * 64 + pg * 16;
                #pragma unroll
                for (int e = 0; e < 4; e++) {
                    float4 o;
                    int p = pg * 16 + e * 4;
                    o.x = gelu_exact(s_u[p + 0] * wu + s_v[p + 0] * wv + bk);
                    o.y = gelu_exact(s_u[p + 1] * wu + s_v[p + 1] * wv + bk);
                    o.z = gelu_exact(s_u[p + 2] * wu + s_v[p + 2] * wv + bk);
                    o.w = gelu_exact(s_u[p + 3] * wu + s_v[p + 3] * wv + bk);
                    *(float4*)(dst + e * 4) = o;
                }
            }
            __syncthreads();
        }
    }

    // ---- global barrier: release g_h, wait for all CTAs ----
    __threadfence();
    __syncthreads();
    if (tid == 0) {
        unsigned old = atomicAdd(&g_bar, 1u);
        s_tgt[0] = (old / GRIDMAIN + 1u) * GRIDMAIN;
    }
    __syncthreads();
    const unsigned bar_target = s_tgt[0];
    if (tid == 0) {
        unsigned v;
        do {
            asm volatile("ld.global.acquire.gpu.u32 %0, [%1];"
                         : "=r"(v) : "l"(&g_bar) : "memory");
            if (v >= bar_target) break;
            __nanosleep(64);
        } while (true);
    }
    __syncthreads();

    // ============ PHASE B: point-packed GEMM + epilogue + interleaved zero ============
    auto build = [&](int t, int sel) {
        float* ht = (float*)(smem + (sel ? OFF_HB : OFF_HA));
        char* mb = smem + (sel ? OFF_M1 : OFF_M0);
        int*   m_geom = (int*)mb;
        int*   m_addr = (int*)(mb + 256);
        float* m_wy   = (float*)(mb + 512);
        float* m_wx   = (float*)(mb + 768);

        // stream transposed h tile: 1024 float4, repack to padded stride
        const float4* src = (const float4*)(g_h + (size_t)t * 4096);
        #pragma unroll
        for (int e = 0; e < 4; e++) {
            int idx = tid + TPB * e;             // float4 index
            float4 v = src[idx];
            int k = idx >> 4, p4 = idx & 15;
            *(float4*)(ht + k * HT_STRIDE + p4 * 4) = v;
        }

        if (tid < 64) {
            int q = t * 64 + tid;
            if (q < total) {
                int lo = 0, hi = BATCH;
                while (hi - lo > 1) {
                    int mid = (lo + hi) >> 1;
                    if (q >= s_base[mid]) lo = mid; else hi = mid;
                }
                int b = lo;
                int hw = s_hw[b];
                int H = hw >> 16, W = hw & 0xFFFF;
                int r = q - s_base[b];
                int i = r / W, j = r - i * W;
                float u = (H > 1) ? (float)i / (float)(H - 1) : 0.0f;
                float v = (W > 1) ? (float)j / (float)(W - 1) : 0.0f;
                float sy = fminf(u * (float)(SGRID - 1), (float)(SGRID - 1));
                float sx = fminf(v * (float)(SGRID - 1), (float)(SGRID - 1));
                int y0 = (int)sy, x0 = (int)sx;
                int y1 = min(y0 + 1, SGRID - 1);
                int x1 = min(x0 + 1, SGRID - 1);
                m_wy[tid] = sy - (float)y0;
                m_wx[tid] = sx - (float)x0;
                m_geom[tid] = y0 | (y1 << 8) | (x0 << 16) | (x1 << 24);
                m_addr[tid] = (b << 11) | (i << 5) | j;
            } else {
                m_wy[tid] = 0.f; m_wx[tid] = 0.f;
                m_geom[tid] = 0;
                m_addr[tid] = -1;
            }
        }
    };

    int zr = blockIdx.x;       // zero/mask row cursor

    if (t0 * 64 < total) build(t0, 0);
    __syncthreads();

    int sel = 0;
    for (int t = t0; t * 64 < total; t += TSTRIDE) {
        const float* ht = (const float*)(smem + (sel ? OFF_HB : OFF_HA));
        const char* mb = smem + (sel ? OFF_M1 : OFF_M0);
        const int*   m_geom = (const int*)mb;
        const int*   m_addr = (const int*)(mb + 256);
        const float* m_wy   = (const float*)(mb + 512);
        const float* m_wx   = (const float*)(mb + 768);

        // ---- GEMM: acc[pi][dd] = {out[p0][d], out[p1][d]} ----
        ull acc[4][4];
        #pragma unroll
        for (int pi = 0; pi < 4; pi++)
            #pragma unroll
            for (int dd = 0; dd < 4; dd++) acc[pi][dd] = 0ull;

        const float* w2s = (const float*)(smem + OFF_W2);
        const int dlane = 4 * nx;                 // 4 contiguous d per thread

        #pragma unroll 8
        for (int k = 0; k < HID; k++) {
            float4 wq = *(const float4*)(w2s + k * 128 + dlane);
            ull wd0 = dupf(wq.x), wd1 = dupf(wq.y), wd2 = dupf(wq.z), wd3 = dupf(wq.w);
            const ulonglong2* hp = (const ulonglong2*)(ht + k * HT_STRIDE + 8 * wid);
            ulonglong2 hA = hp[0], hB = hp[1];    // point-pairs 0,1,2,3 (broadcast)
            ull ph0 = hA.x, ph1 = hA.y, ph2 = hB.x, ph3 = hB.y;
            #define FF(pi, ph) \
                asm("fma.rn.f32x2 %0, %1, %2, %3;" : "=l"(acc[pi][0]) : "l"(ph), "l"(wd0), "l"(acc[pi][0])); \
                asm("fma.rn.f32x2 %0, %1, %2, %3;" : "=l"(acc[pi][1]) : "l"(ph), "l"(wd1), "l"(acc[pi][1])); \
                asm("fma.rn.f32x2 %0, %1, %2, %3;" : "=l"(acc[pi][2]) : "l"(ph), "l"(wd2), "l"(acc[pi][2])); \
                asm("fma.rn.f32x2 %0, %1, %2, %3;" : "=l"(acc[pi][3]) : "l"(ph), "l"(wd3), "l"(acc[pi][3]));
            FF(0, ph0) FF(1, ph1) FF(2, ph2) FF(3, ph3)
            #undef FF
        }

        // ---- epilogue: per point, bilinear + unpacked acc + b2, STG.128 ----
        {
            const float4 b2v = *(const float4*)((const float*)(smem + OFF_B2) + dlane);
            const float* canq = canonical + qtr * 128 + dlane;
            const int pbase = wid * 8;

            #pragma unroll
            for (int pi = 0; pi < 4; pi++) {
                #pragma unroll
                for (int hlf = 0; hlf < 2; hlf++) {
                    int p = pbase + 2 * pi + hlf;
                    int ad = m_addr[p];
                    if (ad < 0) continue;
                    int geom = m_geom[p];
                    int y0 = geom & 0xFF, y1 = (geom >> 8) & 0xFF;
                    int x0 = (geom >> 16) & 0xFF, x1 = (geom >> 24) & 0xFF;
                    float wy = m_wy[p], wx = m_wx[p];
                    float4 q00 = __ldg((const float4*)(canq + (y0 * SGRID + x0) * DIM));
                    float4 q01 = __ldg((const float4*)(canq + (y0 * SGRID + x1) * DIM));
                    float4 q10 = __ldg((const float4*)(canq + (y1 * SGRID + x0) * DIM));
                    float4 q11 = __ldg((const float4*)(canq + (y1 * SGRID + x1) * DIM));
                    float w00 = (1.f - wy) * (1.f - wx), w01 = (1.f - wy) * wx;
                    float w10 = wy * (1.f - wx),         w11 = wy * wx;
                    float a0, a1, a2, a3;
                    if (hlf == 0) {
                        a0 = __uint_as_float((unsigned)acc[pi][0]);
                        a1 = __uint_as_float((unsigned)acc[pi][1]);
                        a2 = __uint_as_float((unsigned)acc[pi][2]);
                        a3 = __uint_as_float((unsigned)acc[pi][3]);
                    } else {
                        a0 = __uint_as_float((unsigned)(acc[pi][0] >> 32));
                        a1 = __uint_as_float((unsigned)(acc[pi][1] >> 32));
                        a2 = __uint_as_float((unsigned)(acc[pi][2] >> 32));
                        a3 = __uint_as_float((unsigned)(acc[pi][3] >> 32));
                    }
                    float4 r;
                    r.x = w00 * q00.x + w01 * q01.x + w10 * q10.x + w11 * q11.x + a0 + b2v.x;
                    r.y = w00 * q00.y + w01 * q01.y + w10 * q10.y + w11 * q11.y + a1 + b2v.y;
                    r.z = w00 * q00.z + w01 * q01.z + w10 * q10.z + w11 * q11.z + a2 + b2v.z;
                    r.w = w00 * q00.w + w01 * q01.w + w10 * q10.w + w11 * q11.w + a3 + b2v.w;
                    *(float4*)(out + (size_t)ad * DIM + qtr * 128 + dlane) = r;
                }
            }
        }

        // ---- zero/mask rows first (STG drains under build's LDG stream) ----
        #pragma unroll 1
        for (int z = 0; z < 3 && zr < NROWS; z++, zr += GRIDMAIN)
            do_row(zr, s_hw, out, mout, tail, tid);

        // ---- build next tile into other buffer ----
        if ((t + TSTRIDE) * 64 < total) build(t + TSTRIDE, sel ^ 1);

        __syncthreads();
        sel ^= 1;
    }

    // ---- remaining zero/mask rows ----
    #pragma unroll 1
    while (zr < NROWS) { do_row(zr, s_hw, out, mout, tail, tid); zr += GRIDMAIN; }

    // ---- padding past mask region (CTA 0) ----
    if (blockIdx.x == 0 && tail > NROWS * 32) {
        for (int e = NROWS * 32 + tid; e < tail; e += TPB)
            mout[e] = 0.0f;
    }
}

extern "C" void kernel_launch(void* const* d_in, const int* in_sizes, int n_in,
                              void* d_out, int out_size)
{
    const float* canonical = (const float*)d_in[0];
    const float* w1        = (const float*)d_in[1];
    const float* b1        = (const float*)d_in[2];
    const float* w2        = (const float*)d_in[3];
    const float* b2        = (const float*)d_in[4];
    const int*   th        = (const int*)d_in[6];
    const int*   tw        = (const int*)d_in[7];
    float* out = (float*)d_out;

    cudaFuncSetAttribute(hgq_all, cudaFuncAttributeMaxDynamicSharedMemorySize, SMEM_BYTES);
    hgq_all<<<GRIDMAIN, TPB, SMEM_BYTES>>>(canonical, w1, b1, w2, b2, th, tw,
                                           out, out_size);
}

// round 15
// speedup vs baseline: 1.3309x; 1.1103x over previous
#include <cuda_runtime.h>
#include <cuda_bf16.h>
#include <cstdint>

// ---------------- problem constants ----------------
#define BATCH   64
#define MAXH    64
#define MAXW    32
#define DIM     512
#define SGRID   8
#define HID     64

#define TPB       256
#define GRIDMAIN  444      // 3 CTAs/SM x 148 SMs — ALL resident (global barrier safe)
#define TSTRIDE   111      // GRIDMAIN / 4 quarters
#define QELEMS    (BATCH * MAXH * MAXW * DIM)
#define NROWS     (BATCH * MAXH)          // 4096 (b,i) row units

// SMEM layout (bytes) — quarter-N, HMMA fragments
#define OFF_BHI   0        // w2_hi B-frags [ks4][nbg16][lane32][2] u32   (16384)
#define OFF_BLO   16384    // w2_lo B-frags                              (16384)
#define OFF_HA    32768    // h frag buf0: hhi 8KB + hlo 8KB             (16384)
#define OFF_HB    49152    // h frag buf1                                (16384)
#define OFF_B2    65536    // b2 quarter [128] fp32                      (512)
#define OFF_M0    66048    // meta buf0 / phase-A u,v                    (1024)
#define OFF_M1    67072    // meta buf1 / barrier scratch                (1024)
#define OFF_BASE  68096    // s_base[65]                                 (260)
#define OFF_HW    68356    // s_hw[64]                                   (256)
#define OFF_W1U   68612
#define OFF_W1V   68868
#define OFF_B1    69124
#define SMEM_BYTES 69632   // x3 = 208896 <= 227KB

typedef unsigned long long ull;

// A-fragment-ordered compacted h: per tile 4096 u32 (hhi 2048 | hlo 2048)
__device__ __align__(16) unsigned g_h[BATCH * MAXH * MAXW * HID];
__device__ unsigned g_bar = 0;     // rolling global barrier counter

__device__ __forceinline__ float gelu_exact(float x) {
    return 0.5f * x * (1.0f + erff(x * 0.70710678118654752440f));
}

__device__ __forceinline__ unsigned pack2(float a, float b) {
    __nv_bfloat162 t = __floats2bfloat162_rn(a, b);
    return *(unsigned*)&t;
}

// m16n8k16 bf16 MMA, f32 accum (classic HMMA path, legal on plain sm_103)
__device__ __forceinline__ void mma16816(float* d, const unsigned* a, const unsigned* b) {
    asm volatile(
        "mma.sync.aligned.m16n8k16.row.col.f32.bf16.bf16.f32 "
        "{%0,%1,%2,%3}, {%4,%5,%6,%7}, {%8,%9}, {%0,%1,%2,%3};"
        : "+f"(d[0]), "+f"(d[1]), "+f"(d[2]), "+f"(d[3])
        : "r"(a[0]), "r"(a[1]), "r"(a[2]), "r"(a[3]), "r"(b[0]), "r"(b[1]));
}

// zero/mask one (b,i) row unit
__device__ __forceinline__ void do_row(
    int r, const int* s_hw, float* __restrict__ out,
    float* __restrict__ mout, int tail, int tid)
{
    const int b = r >> 6, i = r & 63;
    const int hw = s_hw[b];
    const int H = hw >> 16, W = hw & 0xFFFF;
    float4* row = (float4*)(out + ((size_t)r) * (MAXW * DIM));
    const float4 z = make_float4(0.f, 0.f, 0.f, 0.f);
    if (i >= H) {
        #pragma unroll
        for (int e = 0; e < (MAXW * DIM / 4) / TPB; e++)   // 16 iters
            row[tid + TPB * e] = z;
    } else if (W < MAXW) {
        int start4 = W * (DIM / 4);
        int cnt4 = (MAXW - W) * (DIM / 4);
        for (int e = tid; e < cnt4; e += TPB)
            row[start4 + e] = z;
    }
    if (tail > 0 && tid < 32) {
        int idx = r * 32 + tid;
        if (idx < tail)
            mout[idx] = (i < H && tid < W) ? 1.0f : 0.0f;
    }
}

// ---------------- single fused persistent kernel ----------------
__global__ __launch_bounds__(TPB, 3) void hgq_all(
    const float* __restrict__ canonical,   // [8,8,512]
    const float* __restrict__ w1,          // [2,64]
    const float* __restrict__ b1,          // [64]
    const float* __restrict__ w2,          // [64,512]
    const float* __restrict__ b2,          // [512]
    const int*   __restrict__ th,
    const int*   __restrict__ tw,
    float*       __restrict__ out,         // [64,64,32,512] (+ mask tail)
    int          out_size)
{
    extern __shared__ char smem[];
    int*   s_base = (int*)(smem + OFF_BASE);   // [65]
    int*   s_hw   = (int*)(smem + OFF_HW);     // [64]
    float* s_w1u  = (float*)(smem + OFF_W1U);
    float* s_w1v  = (float*)(smem + OFF_W1V);
    float* s_b1   = (float*)(smem + OFF_B1);
    volatile unsigned* s_tgt = (unsigned*)(smem + OFF_M1);

    const int tid  = threadIdx.x;
    const int wid  = tid >> 5;
    const int nx   = tid & 31;
    const int qtr  = blockIdx.x & 3;
    const int t0   = blockIdx.x >> 2;
    const int tail = out_size - QELEMS;
    float* mout = out + QELEMS;

    // ---- one-time staging: small tables ----
    {
        if (tid < 32)
            ((float4*)(smem + OFF_B2))[tid] = __ldg((const float4*)(b2 + qtr * 128) + tid);
        if (tid < 64) {
            s_w1u[tid] = __ldg(w1 + tid);
            s_w1v[tid] = __ldg(w1 + HID + tid);
            s_b1[tid]  = __ldg(b1 + tid);
            int H = min(max(__ldg(th + tid), 1), MAXH);
            int W = min(max(__ldg(tw + tid), 1), MAXW);
            s_hw[tid] = (H << 16) | W;
        }
    }
    // ---- one-time staging: w2 B-fragments (hi + lo) ----
    {
        uint2* bhi = (uint2*)(smem + OFF_BHI);
        uint2* blo = (uint2*)(smem + OFF_BLO);
        #pragma unroll
        for (int e = 0; e < 8; e++) {
            int s = tid + TPB * e;               // 0..2047 = [ks4][nbg16][lane32]
            int ks   = s >> 9;
            int nbg  = (s >> 5) & 15;
            int lane = s & 31;
            int grp = lane >> 2, tig = lane & 3;
            int n  = qtr * 128 + nbg * 8 + grp;
            int k0 = ks * 16 + 2 * tig;
            float wA = __ldg(w2 + (k0)     * DIM + n);
            float wB = __ldg(w2 + (k0 + 1) * DIM + n);
            float wC = __ldg(w2 + (k0 + 8) * DIM + n);
            float wD = __ldg(w2 + (k0 + 9) * DIM + n);
            __nv_bfloat16 hA = __float2bfloat16(wA), hB = __float2bfloat16(wB);
            __nv_bfloat16 hC = __float2bfloat16(wC), hD = __float2bfloat16(wD);
            unsigned hi0 = (unsigned)__bfloat16_as_ushort(hA) | ((unsigned)__bfloat16_as_ushort(hB) << 16);
            unsigned hi1 = (unsigned)__bfloat16_as_ushort(hC) | ((unsigned)__bfloat16_as_ushort(hD) << 16);
            bhi[s] = make_uint2(hi0, hi1);
            blo[s] = make_uint2(
                pack2(wA - __bfloat162float(hA), wB - __bfloat162float(hB)),
                pack2(wC - __bfloat162float(hC), wD - __bfloat162float(hD)));
        }
    }
    __syncthreads();

    if (wid == 0) {
        int hw0 = s_hw[2 * nx], hw1 = s_hw[2 * nx + 1];
        int c0 = (hw0 >> 16) * (hw0 & 0xFFFF);
        int c1 = (hw1 >> 16) * (hw1 & 0xFFFF);
        int pair = c0 + c1, incl = pair;
        #pragma unroll
        for (int d = 1; d < 32; d <<= 1) {
            int n = __shfl_up_sync(0xFFFFFFFF, incl, d);
            if (nx >= d) incl += n;
        }
        s_base[2 * nx] = incl - pair;
        s_base[2 * nx + 1] = incl - c1;
        if (nx == 31) s_base[64] = incl;
    }
    __syncthreads();
    const int total = s_base[BATCH];

    // ===== PHASE A: gelu h written as A-fragments (hi|lo) per tile =====
    {
        float* s_u = (float*)(smem + OFF_M0);
        float* s_v = (float*)(smem + OFF_M0 + 256);
        for (int tt = blockIdx.x; tt * 64 < total; tt += GRIDMAIN) {
            if (tid < 64) {
                int q = tt * 64 + tid;
                float u = 0.f, v = 0.f;
                if (q < total) {
                    int lo = 0, hi = BATCH;
                    while (hi - lo > 1) {
                        int mid = (lo + hi) >> 1;
                        if (q >= s_base[mid]) lo = mid; else hi = mid;
                    }
                    int hw = s_hw[lo];
                    int H = hw >> 16, W = hw & 0xFFFF;
                    int r = q - s_base[lo];
                    int i = r / W, j = r - i * W;
                    u = (H > 1) ? (float)i / (float)(H - 1) : 0.0f;
                    v = (W > 1) ? (float)j / (float)(W - 1) : 0.0f;
                }
                s_u[tid] = u; s_v[tid] = v;
            }
            __syncthreads();
            {
                uint4* gp = (uint4*)(g_h + (size_t)tt * 4096);
                #pragma unroll
                for (int e = 0; e < 2; e++) {
                    int s = tid * 2 + e;         // 0..511 = [ks4][strip4][lane32]
                    int ks = s >> 7, strip = (s >> 5) & 3, lane = s & 31;
                    int grp = lane >> 2, tig = lane & 3;
                    unsigned hi4[4], lo4[4];
                    #pragma unroll
                    for (int r = 0; r < 4; r++) {
                        int p = strip * 16 + grp + (r & 1) * 8;
                        int k = ks * 16 + 2 * tig + (r >> 1) * 8;
                        float uu = s_u[p], vv = s_v[p];
                        float h0 = gelu_exact(uu * s_w1u[k]     + vv * s_w1v[k]     + s_b1[k]);
                        float h1 = gelu_exact(uu * s_w1u[k + 1] + vv * s_w1v[k + 1] + s_b1[k + 1]);
                        __nv_bfloat16 g0 = __float2bfloat16(h0), g1 = __float2bfloat16(h1);
                        hi4[r] = (unsigned)__bfloat16_as_ushort(g0) | ((unsigned)__bfloat16_as_ushort(g1) << 16);
                        lo4[r] = pack2(h0 - __bfloat162float(g0), h1 - __bfloat162float(g1));
                    }
                    gp[s]       = make_uint4(hi4[0], hi4[1], hi4[2], hi4[3]);
                    gp[512 + s] = make_uint4(lo4[0], lo4[1], lo4[2], lo4[3]);
                }
            }
            __syncthreads();
        }
    }

    // ---- global barrier ----
    __threadfence();
    __syncthreads();
    if (tid == 0) {
        unsigned old = atomicAdd(&g_bar, 1u);
        s_tgt[0] = (old / GRIDMAIN + 1u) * GRIDMAIN;
    }
    __syncthreads();
    const unsigned bar_target = s_tgt[0];
    if (tid == 0) {
        unsigned v;
        do {
            asm volatile("ld.global.acquire.gpu.u32 %0, [%1];"
                         : "=r"(v) : "l"(&g_bar) : "memory");
            if (v >= bar_target) break;
            __nanosleep(64);
        } while (true);
    }
    __syncthreads();

    // ===== PHASE B: HMMA GEMM + epilogue + interleaved zero =====
    auto build = [&](int t, int sel) {
        float4* hbuf = (float4*)(smem + (sel ? OFF_HB : OFF_HA));
        char* mb = smem + (sel ? OFF_M1 : OFF_M0);
        int*   m_geom = (int*)mb;
        int*   m_addr = (int*)(mb + 256);
        float* m_wy   = (float*)(mb + 512);
        float* m_wx   = (float*)(mb + 768);

        // stream fragment tile: 1024 float4, straight copy
        const float4* src = (const float4*)(g_h + (size_t)t * 4096);
        #pragma unroll
        for (int e = 0; e < 4; e++)
            hbuf[tid + TPB * e] = src[tid + TPB * e];

        if (tid < 64) {
            int q = t * 64 + tid;
            if (q < total) {
                int lo = 0, hi = BATCH;
                while (hi - lo > 1) {
                    int mid = (lo + hi) >> 1;
                    if (q >= s_base[mid]) lo = mid; else hi = mid;
                }
                int b = lo;
                int hw = s_hw[b];
                int H = hw >> 16, W = hw & 0xFFFF;
                int r = q - s_base[b];
                int i = r / W, j = r - i * W;
                float u = (H > 1) ? (float)i / (float)(H - 1) : 0.0f;
                float v = (W > 1) ? (float)j / (float)(W - 1) : 0.0f;
                float sy = fminf(u * (float)(SGRID - 1), (float)(SGRID - 1));
                float sx = fminf(v * (float)(SGRID - 1), (float)(SGRID - 1));
                int y0 = (int)sy, x0 = (int)sx;
                int y1 = min(y0 + 1, SGRID - 1);
                int x1 = min(x0 + 1, SGRID - 1);
                m_wy[tid] = sy - (float)y0;
                m_wx[tid] = sx - (float)x0;
                m_geom[tid] = y0 | (y1 << 8) | (x0 << 16) | (x1 << 24);
                m_addr[tid] = (b << 11) | (i << 5) | j;
            } else {
                m_wy[tid] = 0.f; m_wx[tid] = 0.f;
                m_geom[tid] = 0;
                m_addr[tid] = -1;
            }
        }
    };

    int zr = blockIdx.x;       // zero/mask row cursor

    if (t0 * 64 < total) build(t0, 0);
    __syncthreads();

    const int strip = wid & 3;       // m16 strip (points strip*16..+15)
    const int nhalf = wid >> 2;      // n64 half of the 128-d quarter

    int sel = 0;
    for (int t = t0; t * 64 < total; t += TSTRIDE) {
        const char* ht = smem + (sel ? OFF_HB : OFF_HA);
        const char* mb = smem + (sel ? OFF_M1 : OFF_M0);
        const int*   m_geom = (const int*)mb;
        const int*   m_addr = (const int*)(mb + 256);
        const float* m_wy   = (const float*)(mb + 512);
        const float* m_wx   = (const float*)(mb + 768);

        // ---- HMMA GEMM: D[64p x 128d] via m16n8k16, 3-term bf16 split ----
        float acc[8][4];
        #pragma unroll
        for (int nb = 0; nb < 8; nb++)
            #pragma unroll
            for (int r = 0; r < 4; r++) acc[nb][r] = 0.f;

        #pragma unroll
        for (int ks = 0; ks < 4; ks++) {
            unsigned afhi[4], aflo[4];
            {
                uint4 a = *(const uint4*)(ht + (((ks * 4 + strip) * 32 + nx) << 4));
                afhi[0] = a.x; afhi[1] = a.y; afhi[2] = a.z; afhi[3] = a.w;
                uint4 b = *(const uint4*)(ht + 8192 + (((ks * 4 + strip) * 32 + nx) << 4));
                aflo[0] = b.x; aflo[1] = b.y; aflo[2] = b.z; aflo[3] = b.w;
            }
            #pragma unroll
            for (int nb = 0; nb < 8; nb++) {
                int nbg = nhalf * 8 + nb;
                uint2 bh = *(const uint2*)(smem + OFF_BHI + (((ks * 16 + nbg) * 32 + nx) << 3));
                uint2 bl = *(const uint2*)(smem + OFF_BLO + (((ks * 16 + nbg) * 32 + nx) << 3));
                unsigned bhr[2] = {bh.x, bh.y};
                unsigned blr[2] = {bl.x, bl.y};
                mma16816(acc[nb], afhi, bhr);
                mma16816(acc[nb], aflo, bhr);
                mma16816(acc[nb], afhi, blr);
            }
        }

        // ---- epilogue: D frags -> bilinear + b2 + store (float2 per nb) ----
        {
            const int grp = nx >> 2, tig = nx & 3;
            const float* b2q = (const float*)(smem + OFF_B2) + nhalf * 64 + 2 * tig;
            const float* canb = canonical + qtr * 128 + nhalf * 64 + 2 * tig;

            #pragma unroll
            for (int hrow = 0; hrow < 2; hrow++) {
                int p = strip * 16 + grp + hrow * 8;
                int ad = m_addr[p];
                if (ad < 0) continue;
                int geom = m_geom[p];
                int y0 = geom & 0xFF, y1 = (geom >> 8) & 0xFF;
                int x0 = (geom >> 16) & 0xFF, x1 = (geom >> 24) & 0xFF;
                float wy = m_wy[p], wx = m_wx[p];
                float w00 = (1.f - wy) * (1.f - wx), w01 = (1.f - wy) * wx;
                float w10 = wy * (1.f - wx),         w11 = wy * wx;
                const float* c00 = canb + (y0 * SGRID + x0) * DIM;
                const float* c01 = canb + (y0 * SGRID + x1) * DIM;
                const float* c10 = canb + (y1 * SGRID + x0) * DIM;
                const float* c11 = canb + (y1 * SGRID + x1) * DIM;
                float* ob = out + (size_t)ad * DIM + qtr * 128 + nhalf * 64 + 2 * tig;

                #pragma unroll
                for (int nb = 0; nb < 8; nb++) {
                    int nn = nb * 8;
                    float2 q00 = __ldg((const float2*)(c00 + nn));
                    float2 q01 = __ldg((const float2*)(c01 + nn));
                    float2 q10 = __ldg((const float2*)(c10 + nn));
                    float2 q11 = __ldg((const float2*)(c11 + nn));
                    float2 bv  = *(const float2*)(b2q + nn);
                    float2 r;
                    r.x = w00 * q00.x + w01 * q01.x + w10 * q10.x + w11 * q11.x
                        + acc[nb][hrow * 2 + 0] + bv.x;
                    r.y = w00 * q00.y + w01 * q01.y + w10 * q10.y + w11 * q11.y
                        + acc[nb][hrow * 2 + 1] + bv.y;
                    *(float2*)(ob + nn) = r;
                }
            }
        }

        // ---- interleaved zero/mask rows, then build next tile ----
        #pragma unroll 1
        for (int z = 0; z < 3 && zr < NROWS; z++, zr += GRIDMAIN)
            do_row(zr, s_hw, out, mout, tail, tid);

        if ((t + TSTRIDE) * 64 < total) build(t + TSTRIDE, sel ^ 1);

        __syncthreads();
        sel ^= 1;
    }

    // ---- remaining zero/mask rows ----
    #pragma unroll 1
    while (zr < NROWS) { do_row(zr, s_hw, out, mout, tail, tid); zr += GRIDMAIN; }

    // ---- padding past mask region (CTA 0) ----
    if (blockIdx.x == 0 && tail > NROWS * 32) {
        for (int e = NROWS * 32 + tid; e < tail; e += TPB)
            mout[e] = 0.0f;
    }
}

extern "C" void kernel_launch(void* const* d_in, const int* in_sizes, int n_in,
                              void* d_out, int out_size)
{
    const float* canonical = (const float*)d_in[0];
    const float* w1        = (const float*)d_in[1];
    const float* b1        = (const float*)d_in[2];
    const float* w2        = (const float*)d_in[3];
    const float* b2        = (const float*)d_in[4];
    const int*   th        = (const int*)d_in[6];
    const int*   tw        = (const int*)d_in[7];
    float* out = (float*)d_out;

    cudaFuncSetAttribute(hgq_all, cudaFuncAttributeMaxDynamicSharedMemorySize, SMEM_BYTES);
    hgq_all<<<GRIDMAIN, TPB, SMEM_BYTES>>>(canonical, w1, b1, w2, b2, th, tw,
                                           out, out_size);
}

// round 16
// speedup vs baseline: 1.3990x; 1.0512x over previous
#include <cuda_runtime.h>
#include <cuda_bf16.h>
#include <cstdint>

// ---------------- problem constants ----------------
#define BATCH   64
#define MAXH    64
#define MAXW    32
#define DIM     512
#define SGRID   8
#define HID     64

#define TPB       256
#define GRIDMAIN  444      // 3 CTAs/SM x 148 SMs
#define TSTRIDE   111      // GRIDMAIN / 4 quarters
#define QELEMS    (BATCH * MAXH * MAXW * DIM)
#define NROWS     (BATCH * MAXH)          // 4096 (b,i) row units

// SMEM layout (bytes) — quarter-N, HMMA fragments, in-pipeline gelu
#define OFF_BHI   0        // w2_hi B-frags [ks4][nbg16][lane32][2] u32  (16384)
#define OFF_BLO   16384    // w2_lo B-frags                             (16384)
#define OFF_HA    32768    // h frag buf0: hhi 8KB + hlo 8KB            (16384)
#define OFF_HB    49152    // h frag buf1                               (16384)
#define OFF_B2    65536    // b2 quarter [128] fp32                     (512)
#define OFF_M0    66048    // meta buf0: geom,addr,wy,wx,u,v            (1536)
#define OFF_M1    67584    // meta buf1                                 (1536)
#define OFF_BASE  69120    // s_base[65]                                (260)
#define OFF_HW    69380    // s_hw[64]                                  (256)
#define OFF_W1U   69636
#define OFF_W1V   69892
#define OFF_B1    70148
#define SMEM_BYTES 70656   // x3 = 211968 <= 227KB

typedef unsigned long long ull;

__device__ __forceinline__ float gelu_exact(float x) {
    return 0.5f * x * (1.0f + erff(x * 0.70710678118654752440f));
}

__device__ __forceinline__ unsigned pack2(float a, float b) {
    __nv_bfloat162 t = __floats2bfloat162_rn(a, b);
    return *(unsigned*)&t;
}

// m16n8k16 bf16 MMA, f32 accum (classic HMMA path, legal on plain sm_103)
__device__ __forceinline__ void mma16816(float* d, const unsigned* a, const unsigned* b) {
    asm volatile(
        "mma.sync.aligned.m16n8k16.row.col.f32.bf16.bf16.f32 "
        "{%0,%1,%2,%3}, {%4,%5,%6,%7}, {%8,%9}, {%0,%1,%2,%3};"
        : "+f"(d[0]), "+f"(d[1]), "+f"(d[2]), "+f"(d[3])
        : "r"(a[0]), "r"(a[1]), "r"(a[2]), "r"(a[3]), "r"(b[0]), "r"(b[1]));
}

// zero/mask one (b,i) row unit
__device__ __forceinline__ void do_row(
    int r, const int* s_hw, float* __restrict__ out,
    float* __restrict__ mout, int tail, int tid)
{
    const int b = r >> 6, i = r & 63;
    const int hw = s_hw[b];
    const int H = hw >> 16, W = hw & 0xFFFF;
    float4* row = (float4*)(out + ((size_t)r) * (MAXW * DIM));
    const float4 z = make_float4(0.f, 0.f, 0.f, 0.f);
    if (i >= H) {
        #pragma unroll
        for (int e = 0; e < (MAXW * DIM / 4) / TPB; e++)   // 16 iters
            row[tid + TPB * e] = z;
    } else if (W < MAXW) {
        int start4 = W * (DIM / 4);
        int cnt4 = (MAXW - W) * (DIM / 4);
        for (int e = tid; e < cnt4; e += TPB)
            row[start4 + e] = z;
    }
    if (tail > 0 && tid < 32) {
        int idx = r * 32 + tid;
        if (idx < tail)
            mout[idx] = (i < H && tid < W) ? 1.0f : 0.0f;
    }
}

// ---------------- single fused persistent kernel ----------------
__global__ __launch_bounds__(TPB, 3) void hgq_all(
    const float* __restrict__ canonical,   // [8,8,512]
    const float* __restrict__ w1,          // [2,64]
    const float* __restrict__ b1,          // [64]
    const float* __restrict__ w2,          // [64,512]
    const float* __restrict__ b2,          // [512]
    const int*   __restrict__ th,
    const int*   __restrict__ tw,
    float*       __restrict__ out,         // [64,64,32,512] (+ mask tail)
    int          out_size)
{
    extern __shared__ char smem[];
    int*   s_base = (int*)(smem + OFF_BASE);   // [65]
    int*   s_hw   = (int*)(smem + OFF_HW);     // [64]
    float* s_w1u  = (float*)(smem + OFF_W1U);
    float* s_w1v  = (float*)(smem + OFF_W1V);
    float* s_b1   = (float*)(smem + OFF_B1);

    const int tid  = threadIdx.x;
    const int wid  = tid >> 5;
    const int nx   = tid & 31;
    const int qtr  = blockIdx.x & 3;
    const int t0   = blockIdx.x >> 2;
    const int tail = out_size - QELEMS;
    float* mout = out + QELEMS;

    // ---- one-time staging: small tables ----
    {
        if (tid < 32)
            ((float4*)(smem + OFF_B2))[tid] = __ldg((const float4*)(b2 + qtr * 128) + tid);
        if (tid < 64) {
            s_w1u[tid] = __ldg(w1 + tid);
            s_w1v[tid] = __ldg(w1 + HID + tid);
            s_b1[tid]  = __ldg(b1 + tid);
            int H = min(max(__ldg(th + tid), 1), MAXH);
            int W = min(max(__ldg(tw + tid), 1), MAXW);
            s_hw[tid] = (H << 16) | W;
        }
    }
    // ---- one-time staging: w2 B-fragments (hi + lo) ----
    {
        uint2* bhi = (uint2*)(smem + OFF_BHI);
        uint2* blo = (uint2*)(smem + OFF_BLO);
        #pragma unroll
        for (int e = 0; e < 8; e++) {
            int s = tid + TPB * e;               // 0..2047 = [ks4][nbg16][lane32]
            int ks   = s >> 9;
            int nbg  = (s >> 5) & 15;
            int lane = s & 31;
            int grp = lane >> 2, tig = lane & 3;
            int n  = qtr * 128 + nbg * 8 + grp;
            int k0 = ks * 16 + 2 * tig;
            float wA = __ldg(w2 + (k0)     * DIM + n);
            float wB = __ldg(w2 + (k0 + 1) * DIM + n);
            float wC = __ldg(w2 + (k0 + 8) * DIM + n);
            float wD = __ldg(w2 + (k0 + 9) * DIM + n);
            __nv_bfloat16 hA = __float2bfloat16(wA), hB = __float2bfloat16(wB);
            __nv_bfloat16 hC = __float2bfloat16(wC), hD = __float2bfloat16(wD);
            unsigned hi0 = (unsigned)__bfloat16_as_ushort(hA) | ((unsigned)__bfloat16_as_ushort(hB) << 16);
            unsigned hi1 = (unsigned)__bfloat16_as_ushort(hC) | ((unsigned)__bfloat16_as_ushort(hD) << 16);
            bhi[s] = make_uint2(hi0, hi1);
            blo[s] = make_uint2(
                pack2(wA - __bfloat162float(hA), wB - __bfloat162float(hB)),
                pack2(wC - __bfloat162float(hC), wD - __bfloat162float(hD)));
        }
    }
    __syncthreads();

    if (wid == 0) {
        int hw0 = s_hw[2 * nx], hw1 = s_hw[2 * nx + 1];
        int c0 = (hw0 >> 16) * (hw0 & 0xFFFF);
        int c1 = (hw1 >> 16) * (hw1 & 0xFFFF);
        int pair = c0 + c1, incl = pair;
        #pragma unroll
        for (int d = 1; d < 32; d <<= 1) {
            int n = __shfl_up_sync(0xFFFFFFFF, incl, d);
            if (nx >= d) incl += n;
        }
        s_base[2 * nx] = incl - pair;
        s_base[2 * nx + 1] = incl - c1;
        if (nx == 31) s_base[64] = incl;
    }
    __syncthreads();
    const int total = s_base[BATCH];

    // ---- per-tile build, stage 1: meta + u,v (threads 0..63) ----
    auto buildA = [&](int t, int sel) {
        char* mb = smem + (sel ? OFF_M1 : OFF_M0);
        int*   m_geom = (int*)mb;
        int*   m_addr = (int*)(mb + 256);
        float* m_wy   = (float*)(mb + 512);
        float* m_wx   = (float*)(mb + 768);
        float* m_u    = (float*)(mb + 1024);
        float* m_v    = (float*)(mb + 1280);

        if (tid < 64) {
            int q = t * 64 + tid;
            if (q < total) {
                int lo = 0, hi = BATCH;
                while (hi - lo > 1) {
                    int mid = (lo + hi) >> 1;
                    if (q >= s_base[mid]) lo = mid; else hi = mid;
                }
                int b = lo;
                int hw = s_hw[b];
                int H = hw >> 16, W = hw & 0xFFFF;
                int r = q - s_base[b];
                int i = r / W, j = r - i * W;
                float u = (H > 1) ? (float)i / (float)(H - 1) : 0.0f;
                float v = (W > 1) ? (float)j / (float)(W - 1) : 0.0f;
                float sy = fminf(u * (float)(SGRID - 1), (float)(SGRID - 1));
                float sx = fminf(v * (float)(SGRID - 1), (float)(SGRID - 1));
                int y0 = (int)sy, x0 = (int)sx;
                int y1 = min(y0 + 1, SGRID - 1);
                int x1 = min(x0 + 1, SGRID - 1);
                m_wy[tid] = sy - (float)y0;
                m_wx[tid] = sx - (float)x0;
                m_geom[tid] = y0 | (y1 << 8) | (x0 << 16) | (x1 << 24);
                m_addr[tid] = (b << 11) | (i << 5) | j;
                m_u[tid] = u; m_v[tid] = v;
            } else {
                m_wy[tid] = 0.f; m_wx[tid] = 0.f;
                m_geom[tid] = 0;
                m_addr[tid] = -1;
                m_u[tid] = 0.f; m_v[tid] = 0.f;
            }
        }
    };

    // ---- per-tile build, stage 2: gelu -> A-fragments (all threads) ----
    auto buildB = [&](int sel) {
        char* ht = smem + (sel ? OFF_HB : OFF_HA);
        const char* mb = smem + (sel ? OFF_M1 : OFF_M0);
        const float* m_u = (const float*)(mb + 1024);
        const float* m_v = (const float*)(mb + 1280);

        #pragma unroll
        for (int e = 0; e < 2; e++) {
            int s = tid + TPB * e;               // 0..511 = [ks4][strip4][lane32]
            int ks = s >> 7, strip = (s >> 5) & 3, lane = s & 31;
            int grp = lane >> 2, tig = lane & 3;
            unsigned hi4[4], lo4[4];
            #pragma unroll
            for (int r = 0; r < 4; r++) {
                int p = strip * 16 + grp + (r & 1) * 8;
                int k = ks * 16 + 2 * tig + (r >> 1) * 8;
                float uu = m_u[p], vv = m_v[p];
                float h0 = gelu_exact(uu * s_w1u[k]     + vv * s_w1v[k]     + s_b1[k]);
                float h1 = gelu_exact(uu * s_w1u[k + 1] + vv * s_w1v[k + 1] + s_b1[k + 1]);
                __nv_bfloat16 g0 = __float2bfloat16(h0), g1 = __float2bfloat16(h1);
                hi4[r] = (unsigned)__bfloat16_as_ushort(g0) | ((unsigned)__bfloat16_as_ushort(g1) << 16);
                lo4[r] = pack2(h0 - __bfloat162float(g0), h1 - __bfloat162float(g1));
            }
            *(uint4*)(ht + (s << 4))        = make_uint4(hi4[0], hi4[1], hi4[2], hi4[3]);
            *(uint4*)(ht + 8192 + (s << 4)) = make_uint4(lo4[0], lo4[1], lo4[2], lo4[3]);
        }
    };

    int zr = blockIdx.x;       // zero/mask row cursor

    // prologue: build first tile
    if (t0 * 64 < total) {
        buildA(t0, 0);
        __syncthreads();
        buildB(0);
    }
    __syncthreads();

    const int strip = wid & 3;       // m16 strip (points strip*16..+15)
    const int nhalf = wid >> 2;      // n64 half of the 128-d quarter

    int sel = 0;
    for (int t = t0; t * 64 < total; t += TSTRIDE) {
        const char* ht = smem + (sel ? OFF_HB : OFF_HA);
        const char* mb = smem + (sel ? OFF_M1 : OFF_M0);
        const int*   m_geom = (const int*)mb;
        const int*   m_addr = (const int*)(mb + 256);
        const float* m_wy   = (const float*)(mb + 512);
        const float* m_wx   = (const float*)(mb + 768);

        // ---- HMMA GEMM: D[64p x 128d] via m16n8k16, 3-term bf16 split ----
        float acc[8][4];
        #pragma unroll
        for (int nb = 0; nb < 8; nb++)
            #pragma unroll
            for (int r = 0; r < 4; r++) acc[nb][r] = 0.f;

        #pragma unroll
        for (int ks = 0; ks < 4; ks++) {
            unsigned afhi[4], aflo[4];
            {
                uint4 a = *(const uint4*)(ht + (((ks * 4 + strip) * 32 + nx) << 4));
                afhi[0] = a.x; afhi[1] = a.y; afhi[2] = a.z; afhi[3] = a.w;
                uint4 b = *(const uint4*)(ht + 8192 + (((ks * 4 + strip) * 32 + nx) << 4));
                aflo[0] = b.x; aflo[1] = b.y; aflo[2] = b.z; aflo[3] = b.w;
            }
            #pragma unroll
            for (int nb = 0; nb < 8; nb++) {
                int nbg = nhalf * 8 + nb;
                uint2 bh = *(const uint2*)(smem + OFF_BHI + (((ks * 16 + nbg) * 32 + nx) << 3));
                uint2 bl = *(const uint2*)(smem + OFF_BLO + (((ks * 16 + nbg) * 32 + nx) << 3));
                unsigned bhr[2] = {bh.x, bh.y};
                unsigned blr[2] = {bl.x, bl.y};
                mma16816(acc[nb], afhi, bhr);
                mma16816(acc[nb], aflo, bhr);
                mma16816(acc[nb], afhi, blr);
            }
        }

        // ---- epilogue: D frags -> bilinear + b2 + store (float2 per nb) ----
        {
            const int grp = nx >> 2, tig = nx & 3;
            const float* b2q = (const float*)(smem + OFF_B2) + nhalf * 64 + 2 * tig;
            const float* canb = canonical + qtr * 128 + nhalf * 64 + 2 * tig;

            #pragma unroll
            for (int hrow = 0; hrow < 2; hrow++) {
                int p = strip * 16 + grp + hrow * 8;
                int ad = m_addr[p];
                if (ad < 0) continue;
                int geom = m_geom[p];
                int y0 = geom & 0xFF, y1 = (geom >> 8) & 0xFF;
                int x0 = (geom >> 16) & 0xFF, x1 = (geom >> 24) & 0xFF;
                float wy = m_wy[p], wx = m_wx[p];
                float w00 = (1.f - wy) * (1.f - wx), w01 = (1.f - wy) * wx;
                float w10 = wy * (1.f - wx),         w11 = wy * wx;
                const float* c00 = canb + (y0 * SGRID + x0) * DIM;
                const float* c01 = canb + (y0 * SGRID + x1) * DIM;
                const float* c10 = canb + (y1 * SGRID + x0) * DIM;
                const float* c11 = canb + (y1 * SGRID + x1) * DIM;
                float* ob = out + (size_t)ad * DIM + qtr * 128 + nhalf * 64 + 2 * tig;

                #pragma unroll
                for (int nb = 0; nb < 8; nb++) {
                    int nn = nb * 8;
                    float2 q00 = __ldg((const float2*)(c00 + nn));
                    float2 q01 = __ldg((const float2*)(c01 + nn));
                    float2 q10 = __ldg((const float2*)(c10 + nn));
                    float2 q11 = __ldg((const float2*)(c11 + nn));
                    float2 bv  = *(const float2*)(b2q + nn);
                    float2 r;
                    r.x = w00 * q00.x + w01 * q01.x + w10 * q10.x + w11 * q11.x
                        + acc[nb][hrow * 2 + 0] + bv.x;
                    r.y = w00 * q00.y + w01 * q01.y + w10 * q10.y + w11 * q11.y
                        + acc[nb][hrow * 2 + 1] + bv.y;
                    *(float2*)(ob + nn) = r;
                }
            }
        }

        // ---- interleaved zero/mask rows ----
        #pragma unroll 1
        for (int z = 0; z < 3 && zr < NROWS; z++, zr += GRIDMAIN)
            do_row(zr, s_hw, out, mout, tail, tid);

        // ---- build next tile (meta, sync, gelu->fragments) ----
        const bool more = (t + TSTRIDE) * 64 < total;
        if (more) buildA(t + TSTRIDE, sel ^ 1);
        __syncthreads();
        if (more) buildB(sel ^ 1);
        __syncthreads();
        sel ^= 1;
    }

    // ---- remaining zero/mask rows ----
    #pragma unroll 1
    while (zr < NROWS) { do_row(zr, s_hw, out, mout, tail, tid); zr += GRIDMAIN; }

    // ---- padding past mask region (CTA 0) ----
    if (blockIdx.x == 0 && tail > NROWS * 32) {
        for (int e = NROWS * 32 + tid; e < tail; e += TPB)
            mout[e] = 0.0f;
    }
}

extern "C" void kernel_launch(void* const* d_in, const int* in_sizes, int n_in,
                              void* d_out, int out_size)
{
    const float* canonical = (const float*)d_in[0];
    const float* w1        = (const float*)d_in[1];
    const float* b1        = (const float*)d_in[2];
    const float* w2        = (const float*)d_in[3];
    const float* b2        = (const float*)d_in[4];
    const int*   th        = (const int*)d_in[6];
    const int*   tw        = (const int*)d_in[7];
    float* out = (float*)d_out;

    cudaFuncSetAttribute(hgq_all, cudaFuncAttributeMaxDynamicSharedMemorySize, SMEM_BYTES);
    hgq_all<<<GRIDMAIN, TPB, SMEM_BYTES>>>(canonical, w1, b1, w2, b2, th, tw,
                                           out, out_size);
}

// round 17
// speedup vs baseline: 1.5217x; 1.0877x over previous
#include <cuda_runtime.h>
#include <cuda_bf16.h>
#include <cstdint>

// ---------------- problem constants ----------------
#define BATCH   64
#define MAXH    64
#define MAXW    32
#define DIM     512
#define SGRID   8
#define HID     64

#define TPB       256
#define GRIDMAIN  444      // 3 CTAs/SM x 148 SMs
#define TSTRIDE   111      // GRIDMAIN / 4 quarters
#define QELEMS    (BATCH * MAXH * MAXW * DIM)
#define NROWS     (BATCH * MAXH)          // 4096 (b,i) row units

// SMEM layout (bytes) — quarter-N, HMMA fragments, staged epilogue
#define OFF_BHI   0        // w2_hi B-frags [ks4][nbg16][lane32][2] u32  (16384)
#define OFF_BLO   16384    // w2_lo B-frags                             (16384)
#define OFF_HT    32768    // h fragment buffer (16384); STAGE = [HT, HT+32768)
#define OFF_B2    65536    // b2 quarter [128] fp32                     (512)
#define OFF_M0    66048    // meta buf0: geom,addr,wy,wx,u,v            (1536)
#define OFF_M1    67584    // meta buf1                                 (1536)
#define OFF_BASE  69120    // s_base[65]                                (260)
#define OFF_HW    69380    // s_hw[64]                                  (256)
#define OFF_W1U   69636
#define OFF_W1V   69892
#define OFF_B1    70148
#define SMEM_BYTES 70656   // x3 = 211968 <= 227KB

typedef unsigned long long ull;

__device__ __forceinline__ float gelu_exact(float x) {
    return 0.5f * x * (1.0f + erff(x * 0.70710678118654752440f));
}

__device__ __forceinline__ unsigned pack2(float a, float b) {
    __nv_bfloat162 t = __floats2bfloat162_rn(a, b);
    return *(unsigned*)&t;
}

// m16n8k16 bf16 MMA, f32 accum (classic HMMA path, legal on plain sm_103)
__device__ __forceinline__ void mma16816(float* d, const unsigned* a, const unsigned* b) {
    asm volatile(
        "mma.sync.aligned.m16n8k16.row.col.f32.bf16.bf16.f32 "
        "{%0,%1,%2,%3}, {%4,%5,%6,%7}, {%8,%9}, {%0,%1,%2,%3};"
        : "+f"(d[0]), "+f"(d[1]), "+f"(d[2]), "+f"(d[3])
        : "r"(a[0]), "r"(a[1]), "r"(a[2]), "r"(a[3]), "r"(b[0]), "r"(b[1]));
}

// zero/mask one (b,i) row unit
__device__ __forceinline__ void do_row(
    int r, const int* s_hw, float* __restrict__ out,
    float* __restrict__ mout, int tail, int tid)
{
    const int b = r >> 6, i = r & 63;
    const int hw = s_hw[b];
    const int H = hw >> 16, W = hw & 0xFFFF;
    float4* row = (float4*)(out + ((size_t)r) * (MAXW * DIM));
    const float4 z = make_float4(0.f, 0.f, 0.f, 0.f);
    if (i >= H) {
        #pragma unroll
        for (int e = 0; e < (MAXW * DIM / 4) / TPB; e++)   // 16 iters
            row[tid + TPB * e] = z;
    } else if (W < MAXW) {
        int start4 = W * (DIM / 4);
        int cnt4 = (MAXW - W) * (DIM / 4);
        for (int e = tid; e < cnt4; e += TPB)
            row[start4 + e] = z;
    }
    if (tail > 0 && tid < 32) {
        int idx = r * 32 + tid;
        if (idx < tail)
            mout[idx] = (i < H && tid < W) ? 1.0f : 0.0f;
    }
}

// ---------------- single fused persistent kernel ----------------
__global__ __launch_bounds__(TPB, 3) void hgq_all(
    const float* __restrict__ canonical,   // [8,8,512]
    const float* __restrict__ w1,          // [2,64]
    const float* __restrict__ b1,          // [64]
    const float* __restrict__ w2,          // [64,512]
    const float* __restrict__ b2,          // [512]
    const int*   __restrict__ th,
    const int*   __restrict__ tw,
    float*       __restrict__ out,         // [64,64,32,512] (+ mask tail)
    int          out_size)
{
    extern __shared__ char smem[];
    int*   s_base = (int*)(smem + OFF_BASE);   // [65]
    int*   s_hw   = (int*)(smem + OFF_HW);     // [64]
    float* s_w1u  = (float*)(smem + OFF_W1U);
    float* s_w1v  = (float*)(smem + OFF_W1V);
    float* s_b1   = (float*)(smem + OFF_B1);

    const int tid  = threadIdx.x;
    const int wid  = tid >> 5;
    const int nx   = tid & 31;
    const int qtr  = blockIdx.x & 3;
    const int t0   = blockIdx.x >> 2;
    const int tail = out_size - QELEMS;
    float* mout = out + QELEMS;

    // ---- one-time staging: small tables ----
    {
        if (tid < 32)
            ((float4*)(smem + OFF_B2))[tid] = __ldg((const float4*)(b2 + qtr * 128) + tid);
        if (tid < 64) {
            s_w1u[tid] = __ldg(w1 + tid);
            s_w1v[tid] = __ldg(w1 + HID + tid);
            s_b1[tid]  = __ldg(b1 + tid);
            int H = min(max(__ldg(th + tid), 1), MAXH);
            int W = min(max(__ldg(tw + tid), 1), MAXW);
            s_hw[tid] = (H << 16) | W;
        }
    }
    // ---- one-time staging: w2 B-fragments (hi + lo) ----
    {
        uint2* bhi = (uint2*)(smem + OFF_BHI);
        uint2* blo = (uint2*)(smem + OFF_BLO);
        #pragma unroll
        for (int e = 0; e < 8; e++) {
            int s = tid + TPB * e;               // 0..2047 = [ks4][nbg16][lane32]
            int ks   = s >> 9;
            int nbg  = (s >> 5) & 15;
            int lane = s & 31;
            int grp = lane >> 2, tig = lane & 3;
            int n  = qtr * 128 + nbg * 8 + grp;
            int k0 = ks * 16 + 2 * tig;
            float wA = __ldg(w2 + (k0)     * DIM + n);
            float wB = __ldg(w2 + (k0 + 1) * DIM + n);
            float wC = __ldg(w2 + (k0 + 8) * DIM + n);
            float wD = __ldg(w2 + (k0 + 9) * DIM + n);
            __nv_bfloat16 hA = __float2bfloat16(wA), hB = __float2bfloat16(wB);
            __nv_bfloat16 hC = __float2bfloat16(wC), hD = __float2bfloat16(wD);
            unsigned hi0 = (unsigned)__bfloat16_as_ushort(hA) | ((unsigned)__bfloat16_as_ushort(hB) << 16);
            unsigned hi1 = (unsigned)__bfloat16_as_ushort(hC) | ((unsigned)__bfloat16_as_ushort(hD) << 16);
            bhi[s] = make_uint2(hi0, hi1);
            blo[s] = make_uint2(
                pack2(wA - __bfloat162float(hA), wB - __bfloat162float(hB)),
                pack2(wC - __bfloat162float(hC), wD - __bfloat162float(hD)));
        }
    }
    __syncthreads();

    if (wid == 0) {
        int hw0 = s_hw[2 * nx], hw1 = s_hw[2 * nx + 1];
        int c0 = (hw0 >> 16) * (hw0 & 0xFFFF);
        int c1 = (hw1 >> 16) * (hw1 & 0xFFFF);
        int pair = c0 + c1, incl = pair;
        #pragma unroll
        for (int d = 1; d < 32; d <<= 1) {
            int n = __shfl_up_sync(0xFFFFFFFF, incl, d);
            if (nx >= d) incl += n;
        }
        s_base[2 * nx] = incl - pair;
        s_base[2 * nx + 1] = incl - c1;
        if (nx == 31) s_base[64] = incl;
    }
    __syncthreads();
    const int total = s_base[BATCH];

    // ---- per-tile build, stage 1: meta + u,v (threads 0..63) ----
    auto buildA = [&](int t, int sel) {
        char* mb = smem + (sel ? OFF_M1 : OFF_M0);
        int*   m_geom = (int*)mb;
        int*   m_addr = (int*)(mb + 256);
        float* m_wy   = (float*)(mb + 512);
        float* m_wx   = (float*)(mb + 768);
        float* m_u    = (float*)(mb + 1024);
        float* m_v    = (float*)(mb + 1280);

        if (tid < 64) {
            int q = t * 64 + tid;
            if (q < total) {
                int lo = 0, hi = BATCH;
                while (hi - lo > 1) {
                    int mid = (lo + hi) >> 1;
                    if (q >= s_base[mid]) lo = mid; else hi = mid;
                }
                int b = lo;
                int hw = s_hw[b];
                int H = hw >> 16, W = hw & 0xFFFF;
                int r = q - s_base[b];
                int i = r / W, j = r - i * W;
                float u = (H > 1) ? (float)i / (float)(H - 1) : 0.0f;
                float v = (W > 1) ? (float)j / (float)(W - 1) : 0.0f;
                float sy = fminf(u * (float)(SGRID - 1), (float)(SGRID - 1));
                float sx = fminf(v * (float)(SGRID - 1), (float)(SGRID - 1));
                int y0 = (int)sy, x0 = (int)sx;
                int y1 = min(y0 + 1, SGRID - 1);
                int x1 = min(x0 + 1, SGRID - 1);
                m_wy[tid] = sy - (float)y0;
                m_wx[tid] = sx - (float)x0;
                m_geom[tid] = y0 | (y1 << 8) | (x0 << 16) | (x1 << 24);
                m_addr[tid] = (b << 11) | (i << 5) | j;
                m_u[tid] = u; m_v[tid] = v;
            } else {
                m_wy[tid] = 0.f; m_wx[tid] = 0.f;
                m_geom[tid] = 0;
                m_addr[tid] = -1;
                m_u[tid] = 0.f; m_v[tid] = 0.f;
            }
        }
    };

    // ---- per-tile build, stage 2: gelu -> A-fragments into HT ----
    auto buildB = [&](int sel) {
        char* ht = smem + OFF_HT;
        const char* mb = smem + (sel ? OFF_M1 : OFF_M0);
        const float* m_u = (const float*)(mb + 1024);
        const float* m_v = (const float*)(mb + 1280);

        #pragma unroll
        for (int e = 0; e < 2; e++) {
            int s = tid + TPB * e;               // 0..511 = [ks4][strip4][lane32]
            int ks = s >> 7, strip = (s >> 5) & 3, lane = s & 31;
            int grp = lane >> 2, tig = lane & 3;
            unsigned hi4[4], lo4[4];
            #pragma unroll
            for (int r = 0; r < 4; r++) {
                int p = strip * 16 + grp + (r & 1) * 8;
                int k = ks * 16 + 2 * tig + (r >> 1) * 8;
                float uu = m_u[p], vv = m_v[p];
                float h0 = gelu_exact(uu * s_w1u[k]     + vv * s_w1v[k]     + s_b1[k]);
                float h1 = gelu_exact(uu * s_w1u[k + 1] + vv * s_w1v[k + 1] + s_b1[k + 1]);
                __nv_bfloat16 g0 = __float2bfloat16(h0), g1 = __float2bfloat16(h1);
                hi4[r] = (unsigned)__bfloat16_as_ushort(g0) | ((unsigned)__bfloat16_as_ushort(g1) << 16);
                lo4[r] = pack2(h0 - __bfloat162float(g0), h1 - __bfloat162float(g1));
            }
            *(uint4*)(ht + (s << 4))        = make_uint4(hi4[0], hi4[1], hi4[2], hi4[3]);
            *(uint4*)(ht + 8192 + (s << 4)) = make_uint4(lo4[0], lo4[1], lo4[2], lo4[3]);
        }
    };

    int zr = blockIdx.x;       // zero/mask row cursor

    // prologue: build first tile
    if (t0 * 64 < total) {
        buildA(t0, 0);
        __syncthreads();
        buildB(0);
    }
    __syncthreads();

    const int strip = wid & 3;       // m16 strip (points strip*16..+15)
    const int nhalf = wid >> 2;      // n64 half of the 128-d quarter
    const int grp = nx >> 2, tig = nx & 3;

    int sel = 0;
    for (int t = t0; t * 64 < total; t += TSTRIDE) {
        const char* ht = smem + OFF_HT;
        const char* mb = smem + (sel ? OFF_M1 : OFF_M0);
        const int*   m_geom = (const int*)mb;
        const int*   m_addr = (const int*)(mb + 256);
        const float* m_wy   = (const float*)(mb + 512);
        const float* m_wx   = (const float*)(mb + 768);

        // ---- HMMA GEMM: D[64p x 128d] via m16n8k16, 3-term bf16 split ----
        float acc[8][4];
        #pragma unroll
        for (int nb = 0; nb < 8; nb++)
            #pragma unroll
            for (int r = 0; r < 4; r++) acc[nb][r] = 0.f;

        #pragma unroll
        for (int ks = 0; ks < 4; ks++) {
            unsigned afhi[4], aflo[4];
            {
                uint4 a = *(const uint4*)(ht + (((ks * 4 + strip) * 32 + nx) << 4));
                afhi[0] = a.x; afhi[1] = a.y; afhi[2] = a.z; afhi[3] = a.w;
                uint4 b = *(const uint4*)(ht + 8192 + (((ks * 4 + strip) * 32 + nx) << 4));
                aflo[0] = b.x; aflo[1] = b.y; aflo[2] = b.z; aflo[3] = b.w;
            }
            #pragma unroll
            for (int nb = 0; nb < 8; nb++) {
                int nbg = nhalf * 8 + nb;
                uint2 bh = *(const uint2*)(smem + OFF_BHI + (((ks * 16 + nbg) * 32 + nx) << 3));
                uint2 bl = *(const uint2*)(smem + OFF_BLO + (((ks * 16 + nbg) * 32 + nx) << 3));
                unsigned bhr[2] = {bh.x, bh.y};
                unsigned blr[2] = {bl.x, bl.y};
                mma16816(acc[nb], afhi, bhr);
                mma16816(acc[nb], aflo, bhr);
                mma16816(acc[nb], afhi, blr);
            }
        }
        __syncthreads();   // all fragment reads done; HT area becomes STAGE

        // ---- stage D fragments into [point][128d] with XOR swizzle ----
        {
            char* stage = smem + OFF_HT;        // 32 KB: 64 points x 512 B
            #pragma unroll
            for (int hrow = 0; hrow < 2; hrow++) {
                int p = strip * 16 + grp + hrow * 8;
                unsigned m = (unsigned)(p & 7) << 2;
                char* prow = stage + p * 512;
                #pragma unroll
                for (int nb = 0; nb < 8; nb++) {
                    unsigned uu = (unsigned)(nhalf * 32 + nb * 4 + tig) ^ m;
                    float2 v = make_float2(acc[nb][hrow * 2], acc[nb][hrow * 2 + 1]);
                    *(float2*)(prow + uu * 8) = v;
                }
            }
        }
        __syncthreads();

        // ---- vectorized epilogue: warp = point, lane = float4 of 128d ----
        {
            const char* stage = smem + OFF_HT;
            const float4 b2v = ((const float4*)(smem + OFF_B2))[nx];
            const float* canq = canonical + qtr * 128 + 4 * nx;

            #pragma unroll
            for (int pp = 0; pp < 8; pp++) {
                int p = wid * 8 + pp;
                int ad = m_addr[p];
                if (ad < 0) continue;
                int geom = m_geom[p];
                int y0 = geom & 0xFF, y1 = (geom >> 8) & 0xFF;
                int x0 = (geom >> 16) & 0xFF, x1 = (geom >> 24) & 0xFF;
                float wy = m_wy[p], wx = m_wx[p];
                float w00 = (1.f - wy) * (1.f - wx), w01 = (1.f - wy) * wx;
                float w10 = wy * (1.f - wx),         w11 = wy * wx;
                float4 q00 = __ldg((const float4*)(canq + (y0 * SGRID + x0) * DIM));
                float4 q01 = __ldg((const float4*)(canq + (y0 * SGRID + x1) * DIM));
                float4 q10 = __ldg((const float4*)(canq + (y1 * SGRID + x0) * DIM));
                float4 q11 = __ldg((const float4*)(canq + (y1 * SGRID + x1) * DIM));
                unsigned m = (unsigned)(p & 7) << 2;
                unsigned u0 = ((unsigned)(2 * nx)) ^ m;
                float4 av = *(const float4*)(stage + p * 512 + u0 * 8);
                float4 r;
                r.x = w00 * q00.x + w01 * q01.x + w10 * q10.x + w11 * q11.x + av.x + b2v.x;
                r.y = w00 * q00.y + w01 * q01.y + w10 * q10.y + w11 * q11.y + av.y + b2v.y;
                r.z = w00 * q00.z + w01 * q01.z + w10 * q10.z + w11 * q11.z + av.z + b2v.z;
                r.w = w00 * q00.w + w01 * q01.w + w10 * q10.w + w11 * q11.w + av.w + b2v.w;
                *(float4*)(out + (size_t)ad * DIM + qtr * 128 + 4 * nx) = r;
            }
        }

        // ---- interleaved zero/mask rows ----
        #pragma unroll 1
        for (int z = 0; z < 3 && zr < NROWS; z++, zr += GRIDMAIN)
            do_row(zr, s_hw, out, mout, tail, tid);

        // ---- build next tile (meta, sync, gelu->fragments into HT) ----
        const bool more = (t + TSTRIDE) * 64 < total;
        if (more) buildA(t + TSTRIDE, sel ^ 1);
        __syncthreads();   // STAGE consumed; meta[sel^1] ready
        if (more) buildB(sel ^ 1);
        __syncthreads();
        sel ^= 1;
    }

    // ---- remaining zero/mask rows ----
    #pragma unroll 1
    while (zr < NROWS) { do_row(zr, s_hw, out, mout, tail, tid); zr += GRIDMAIN; }

    // ---- padding past mask region (CTA 0) ----
    if (blockIdx.x == 0 && tail > NROWS * 32) {
        for (int e = NROWS * 32 + tid; e < tail; e += TPB)
            mout[e] = 0.0f;
    }
}

extern "C" void kernel_launch(void* const* d_in, const int* in_sizes, int n_in,
                              void* d_out, int out_size)
{
    const float* canonical = (const float*)d_in[0];
    const float* w1        = (const float*)d_in[1];
    const float* b1        = (const float*)d_in[2];
    const float* w2        = (const float*)d_in[3];
    const float* b2        = (const float*)d_in[4];
    const int*   th        = (const int*)d_in[6];
    const int*   tw        = (const int*)d_in[7];
    float* out = (float*)d_out;

    cudaFuncSetAttribute(hgq_all, cudaFuncAttributeMaxDynamicSharedMemorySize, SMEM_BYTES);
    hgq_all<<<GRIDMAIN, TPB, SMEM_BYTES>>>(canonical, w1, b1, w2, b2, th, tw,
                                           out, out_size);
}